// round 17
// baseline (speedup 1.0000x reference)
#include <cuda_runtime.h>

#define CC 128
#define HH 16
#define WW 16
#define BB 32
#define VV 8192
#define NELEM (BB*CC*HH*WW)   // 1048576 elements (== VV*CC — never size-remap!)
#define SN 5

typedef unsigned long long ull;

__device__ __forceinline__ ull pack2(float lo, float hi){
  ull r; asm("mov.b64 %0, {%1, %2};" : "=l"(r) : "f"(lo), "f"(hi)); return r;
}
__device__ __forceinline__ void unpack2(ull v, float& lo, float& hi){
  asm("mov.b64 {%0, %1}, %2;" : "=f"(lo), "=f"(hi) : "l"(v));
}
// packed dual fp32 FMA (Blackwell FFMA2; lanes independent => bit-exact per-lane fp32)
__device__ __forceinline__ ull fma2(ull a, ull b, ull c){
  ull r; asm("fma.rn.f32x2 %0, %1, %2, %3;" : "=l"(r) : "l"(a), "l"(b), "l"(c)); return r;
}

// ---------------- device scratch (no allocations allowed) ----------------
__device__ float g_rest[NELEM];
__device__ float g_fhat[NELEM];
__device__ float g_x[VV*CC];        // pooled vectors, [n][c], n-major
__device__ float g_esq[VV];
__device__ float g_pd[32768];       // partial min dist per (n, chunk)
__device__ int   g_pi[32768];
__device__ int   g_idx[VV];
__device__ float g_h[NELEM];        // current-scale h (upsampled, pre-phi)
__device__ float g_loss[SN*256];    // per-scale per-conv-block loss partials

// ---------------- init ----------------
__global__ void init_kernel(const float* __restrict__ f){
  int i = blockIdx.x*blockDim.x + threadIdx.x;
  if (i < NELEM){ g_rest[i]=f[i]; g_fhat[i]=0.f; }
}

__global__ void esq_kernel(const float* __restrict__ emb){
  int v = blockIdx.x*blockDim.x + threadIdx.x;
  if (v >= VV) return;
  const float4* r = (const float4*)(emb + (size_t)v*CC);
  float s=0.f;
  #pragma unroll
  for (int q=0;q<CC/4;q++){ float4 e=r[q]; s += e.x*e.x+e.y*e.y+e.z*e.z+e.w*e.w; }
  g_esq[v]=s;
}

// ---------------- avg pool (area interpolate) ----------------
__global__ void pool_kernel(int pn, int N){
  int t = blockIdx.x*blockDim.x + threadIdx.x;
  if (t >= N*CC) return;
  int c = t & (CC-1); int n = t >> 7;
  int pp = pn*pn; int b = n/pp; int r = n - b*pp; int y = r/pn; int x = r - y*pn;
  int s = HH/pn;
  const float* base = g_rest + ((b*CC + c)*HH + y*s)*WW + x*s;
  float sum = 0.f;
  for (int dy=0; dy<s; dy++)
    for (int dx=0; dx<s; dx++)
      sum += base[dy*WW + dx];
  g_x[(size_t)n*CC + c] = sum * (1.f/(float)(s*s));
}

// ---------------- argmin stage A v3: 64n x 128v tiles, 8n x 8v per thread ----------------
// dynamic smem (96KB): xs[128k][64n] (32KB) | es[128k][128v] (64KB)
// Per k per thread: 2 LDS.128 (x) + 2 LDS.128 (e) = 64B -> 32 fma2 = 64 MAC (1.0 B/MAC).
// d = e_sq[v] - 2*sum_k x_k e_k, single ascending-k fma chain => bit-identical to R13-16.
__global__ void __launch_bounds__(128) argmin_stageA(const float* __restrict__ emb,
                                                     int nch, int Nvalid){
  extern __shared__ __align__(16) float dsm[];
  float (*xs)[64]  = (float (*)[64])dsm;              // 32KB
  float (*es)[128] = (float (*)[128])(dsm + 128*64);  // 64KB
  int tid = threadIdx.x;
  int n0 = blockIdx.x * 64;
  int L = VV / nch;
  int vbeg = blockIdx.y * L;

  // fill xs: 64 n-rows x 128 k; thread pair = one row
  {
    int i = tid >> 1, half = (tid & 1)*64;
    const float4* src = (const float4*)(g_x + (size_t)(n0+i)*CC + half);
    #pragma unroll
    for (int q=0;q<16;q++){
      float4 x4 = src[q];
      int k = half + q*4;
      xs[k  ][i]=x4.x; xs[k+1][i]=x4.y; xs[k+2][i]=x4.z; xs[k+3][i]=x4.w;
    }
  }

  float bd[8]; int bi[8];
  #pragma unroll
  for (int i=0;i<8;i++){ bd[i]=3.4e38f; bi[i]=0; }
  int tn = tid & 7, tv = tid >> 3;   // 8 n-groups (8n) x 16 v-groups (8v)
  int nb = tn*8, vb = tv*8;

  for (int sub=0; sub<L; sub+=128){
    int v0 = vbeg + sub;
    __syncthreads();
    {
      // fill es: 128 v-rows x 128 k; one row per thread
      const float4* src = (const float4*)(emb + (size_t)(v0+tid)*CC);
      #pragma unroll
      for (int q=0;q<32;q++){
        float4 e4 = src[q];
        int k = q*4;
        es[k  ][tid]=e4.x; es[k+1][tid]=e4.y; es[k+2][tid]=e4.z; es[k+3][tid]=e4.w;
      }
    }
    __syncthreads();

    ull acc[8][4];   // [n][vpair]
    #pragma unroll
    for (int i=0;i<8;i++)
      #pragma unroll
      for (int j=0;j<4;j++) acc[i][j]=0ull;

    #pragma unroll 2
    for (int k=0;k<128;k++){
      float4 xa = *(const float4*)&xs[k][nb];
      float4 xb = *(const float4*)&xs[k][nb+4];
      const ulonglong2* ep = (const ulonglong2*)&es[k][vb];
      ulonglong2 ea = ep[0], eb = ep[1];
      ull xp[8];
      xp[0]=pack2(xa.x,xa.x); xp[1]=pack2(xa.y,xa.y);
      xp[2]=pack2(xa.z,xa.z); xp[3]=pack2(xa.w,xa.w);
      xp[4]=pack2(xb.x,xb.x); xp[5]=pack2(xb.y,xb.y);
      xp[6]=pack2(xb.z,xb.z); xp[7]=pack2(xb.w,xb.w);
      ull ev[4] = {ea.x, ea.y, eb.x, eb.y};
      #pragma unroll
      for (int i=0;i<8;i++)
        #pragma unroll
        for (int j=0;j<4;j++)
          acc[i][j] = fma2(xp[i], ev[j], acc[i][j]);
    }

    // epilogue: per n, v ascending (pairs then lanes), strict < => first-min
    #pragma unroll
    for (int j2=0;j2<4;j2++){
      int v = v0 + vb + j2*2;
      float eqlo = g_esq[v], eqhi = g_esq[v+1];
      #pragma unroll
      for (int i=0;i<8;i++){
        float alo, ahi; unpack2(acc[i][j2], alo, ahi);
        float dlo = eqlo - 2.f*alo;
        if (dlo < bd[i]){ bd[i]=dlo; bi[i]=v; }
        float dhi = eqhi - 2.f*ahi;
        if (dhi < bd[i]){ bd[i]=dhi; bi[i]=v+1; }
      }
    }
  }

  // block reduce: per n, 16 v-group candidates (scratch carved from es region)
  __syncthreads();
  float* rd = dsm + 128*64;               // 1024 floats
  int*   ri = (int*)(rd + 1024);          // 1024 ints
  #pragma unroll
  for (int i=0;i<8;i++){
    rd[(nb+i)*16 + tv] = bd[i];
    ri[(nb+i)*16 + tv] = bi[i];
  }
  __syncthreads();
  if (tid < 64 && n0 + tid < Nvalid){
    float best = 3.4e38f; int besti = 0x7fffffff;
    #pragma unroll
    for (int t=0;t<16;t++){
      float d = rd[tid*16 + t]; int ii = ri[tid*16 + t];
      if (d < best || (d == best && ii < besti)){ best = d; besti = ii; }
    }
    g_pd[(size_t)(n0+tid)*nch + blockIdx.y] = best;
    g_pi[(size_t)(n0+tid)*nch + blockIdx.y] = besti;
  }
}

__global__ void argmin_stageB(int N, int nch){
  int n = blockIdx.x*blockDim.x + threadIdx.x;
  if (n >= N) return;
  float bd = g_pd[(size_t)n*nch]; int bi = g_pi[(size_t)n*nch];
  for (int c=1;c<nch;c++){
    float d = g_pd[(size_t)n*nch + c]; int ii = g_pi[(size_t)n*nch + c];
    if (d < bd || (d == bd && ii < bi)){ bd = d; bi = ii; }
  }
  g_idx[n] = bi;
}

// ---------------- bicubic upsample (jax cubic: Keys a=-0.5 + tap-sum norm) ----
__device__ __forceinline__ float keysf(float x){
  x = fabsf(x);
  if (x < 1.f) return ((1.5f*x - 2.5f)*x)*x + 1.f;
  if (x < 2.f) return ((-0.5f*x + 2.5f)*x - 4.f)*x + 2.f;
  return 0.f;
}
__device__ __forceinline__ void mkw(int i, int pn, float* w){
  float sf = (i + 0.5f)*((float)pn*(1.f/16.f)) - 0.5f;
  float s = 0.f;
  for (int k=0;k<pn;k++){ float wv = keysf(sf - (float)k); w[k]=wv; s+=wv; }
  float inv = 1.f/s;
  for (int k=0;k<pn;k++) w[k]*=inv;
}

__global__ void upsample_kernel(const float* __restrict__ emb, int pn){
  int t = blockIdx.x*blockDim.x + threadIdx.x;
  if (t >= NELEM) return;
  int c = t & 127; int r = t >> 7;
  int x = r & 15; int y = (r>>4)&15; int b = r>>8;
  float wy[8], wx[8];
  mkw(y, pn, wy); mkw(x, pn, wx);
  const int* idxp = g_idx + b*pn*pn;
  float val = 0.f;
  for (int ky=0; ky<pn; ky++){
    float wyv = wy[ky];
    for (int kx=0; kx<pn; kx++){
      float ww = wyv*wx[kx];
      if (ww != 0.f)
        val += ww * emb[(size_t)idxp[ky*pn+kx]*CC + c];
    }
  }
  g_h[((b*CC+c)*HH+y)*WW+x] = val;
}

__global__ void gather_kernel(const float* __restrict__ emb){
  int t = blockIdx.x*blockDim.x + threadIdx.x;
  if (t >= NELEM) return;
  int c = t & 127; int r = t >> 7;
  int x = r & 15; int y = (r>>4)&15; int b = r>>8;
  g_h[((b*CC+c)*HH+y)*WW+x] = emb[(size_t)g_idx[(b*16+y)*16+x]*CC + c];
}

// ---------------- Phi conv3x3 v2 + blend + residual update + loss partial ----------------
// grid (8 co-groups, 32 batch), 128 threads; thread = co-pair (2 c_out) x image row (16 px).
// Per (cb,q,dy): load 18-float input row once -> 17 pixel-pair packs, reused over dx.
// Per-output accumulation chain = cb -> q -> t9(dy*3+dx) ascending: identical to R16.
__global__ void __launch_bounds__(128) conv_phi_kernel(
    const float* __restrict__ f,
    const float* __restrict__ w,
    const float* __restrict__ bias,
    int si){
  __shared__ float in_s[8*18*18];
  __shared__ float w_s[8][9][16];
  __shared__ float red[128];
  int tid = threadIdx.x;
  int b = blockIdx.y, cog = blockIdx.x;
  int p = tid & 7;     // co-pair 0..7 -> co = cog*16 + 2p(+1)
  int y = tid >> 3;    // image row 0..15

  ull acc0[8], acc1[8];   // 8 pixel-pairs for co0 / co1
  #pragma unroll
  for (int i=0;i<8;i++){ acc0[i]=0ull; acc1[i]=0ull; }

  for (int cb=0; cb<16; cb++){
    __syncthreads();
    for (int idx=tid; idx<8*324; idx+=128){
      int q = idx/324; int r2 = idx - q*324;
      int iy = r2/18 - 1; int ix = r2 - (r2/18)*18 - 1;
      int ci = cb*8 + q;
      float v = 0.f;
      if (iy>=0 && iy<16 && ix>=0 && ix<16)
        v = g_h[((b*CC+ci)*HH+iy)*WW+ix];
      in_s[idx] = v;
    }
    for (int idx=tid; idx<1152; idx+=128){
      int q = idx/144; int r2 = idx - q*144;
      int t9 = r2 >> 4; int co = r2 & 15;
      w_s[q][t9][co] = w[((size_t)(cog*16+co)*CC + cb*8+q)*9 + t9];
    }
    __syncthreads();

    #pragma unroll
    for (int q=0;q<8;q++){
      const float* base = in_s + q*324;
      #pragma unroll
      for (int dy=0;dy<3;dy++){
        const float* rowp = base + (y+dy)*18;
        float row[18];
        #pragma unroll
        for (int c=0;c<18;c++) row[c] = rowp[c];
        ull pk[17];
        #pragma unroll
        for (int c=0;c<17;c++) pk[c] = pack2(row[c], row[c+1]);
        #pragma unroll
        for (int dx=0;dx<3;dx++){
          int t9 = dy*3+dx;
          float w0 = w_s[q][t9][2*p];
          float w1 = w_s[q][t9][2*p+1];
          ull W0 = pack2(w0,w0), W1 = pack2(w1,w1);
          #pragma unroll
          for (int j=0;j<8;j++){
            acc0[j] = fma2(pk[2*j+dx], W0, acc0[j]);
            acc1[j] = fma2(pk[2*j+dx], W1, acc1[j]);
          }
        }
      }
    }
  }

  float lsum = 0.f;
  int co0 = cog*16 + 2*p, co1 = co0 + 1;
  float bs0 = bias[co0], bs1 = bias[co1];
  #pragma unroll
  for (int j=0;j<8;j++){
    float s0lo, s0hi, s1lo, s1hi;
    unpack2(acc0[j], s0lo, s0hi);
    unpack2(acc1[j], s1lo, s1hi);
    int px = 2*j;
    {
      int off = ((b*CC+co0)*HH + y)*WW + px;
      float out = 0.5f*g_h[off] + 0.5f*(s0lo + bs0);
      float fh = g_fhat[off] + out;
      g_fhat[off] = fh; g_rest[off] -= out;
      float d = fh - f[off]; lsum += d*d;
      off++;
      out = 0.5f*g_h[off] + 0.5f*(s0hi + bs0);
      fh = g_fhat[off] + out;
      g_fhat[off] = fh; g_rest[off] -= out;
      d = fh - f[off]; lsum += d*d;
    }
    {
      int off = ((b*CC+co1)*HH + y)*WW + px;
      float out = 0.5f*g_h[off] + 0.5f*(s1lo + bs1);
      float fh = g_fhat[off] + out;
      g_fhat[off] = fh; g_rest[off] -= out;
      float d = fh - f[off]; lsum += d*d;
      off++;
      out = 0.5f*g_h[off] + 0.5f*(s1hi + bs1);
      fh = g_fhat[off] + out;
      g_fhat[off] = fh; g_rest[off] -= out;
      d = fh - f[off]; lsum += d*d;
    }
  }
  red[tid] = lsum;
  __syncthreads();
  for (int s=64; s>0; s>>=1){
    if (tid < s) red[tid] += red[tid+s];
    __syncthreads();
  }
  if (tid==0) g_loss[si*256 + b*8 + cog] = red[0];
}

// ---------------- output + loss (f_hat at [0..N), loss at [N]) ----------------
__global__ void output_kernel(const float* __restrict__ f, float* __restrict__ out, int out_size){
  int i = blockIdx.x*blockDim.x + threadIdx.x;
  if (out_size >= NELEM && i < NELEM)
    out[i] = (g_fhat[i] - f[i]) + f[i];   // straight-through rounding replicated
}

__global__ void loss_kernel(float* __restrict__ out, int out_size){
  __shared__ float m[SN];
  int tid = threadIdx.x;
  if (tid < SN){
    float s = 0.f;
    for (int i=0;i<256;i++) s += g_loss[tid*256+i];
    m[tid] = s * (1.f/(float)NELEM);
  }
  __syncthreads();
  if (tid == 0){
    float loss = 0.f;
    for (int si=0; si<SN; si++) loss += 0.25f*m[si] + m[si];
    loss *= (1.f/(float)SN);
    int pos = -1;
    if (out_size > NELEM) pos = NELEM;
    else if (out_size == 1) pos = 0;
    if (pos >= 0) out[pos] = loss;
  }
}

// ---------------- launch ----------------
extern "C" void kernel_launch(void* const* d_in, const int* in_sizes, int n_in,
                              void* d_out, int out_size){
  // positional inputs only (size-based remap is unsafe: NELEM == VV*CC)
  const float* f   = (const float*)d_in[0];
  const float* emb = (const float*)d_in[1];
  const float* pw  = (const float*)d_in[2];
  const float* pb  = (const float*)d_in[3];
  float* out = (float*)d_out;

  // opt-in to 96KB dynamic smem for stageA (idempotent host API, capture-legal)
  cudaFuncSetAttribute(argmin_stageA, cudaFuncAttributeMaxDynamicSharedMemorySize, 98304);

  init_kernel<<<NELEM/256, 256>>>(f);
  esq_kernel<<<VV/256, 256>>>(emb);

  const int pns[SN]  = {1,2,4,8,16};
  const int chs[SN]  = {64,64,16,8,4};   // v-chunks (L = 8192/chs, multiple of 128)
  const int kphi[SN] = {0,1,2,2,3};      // exact IEEE-754 linspace argmin (R13-verified)

  for (int si=0; si<SN; si++){
    int pn = pns[si];
    int N = BB*pn*pn;
    pool_kernel<<<(N*CC+255)/256, 256>>>(pn, N);
    dim3 ga((N+63)/64, chs[si]);
    argmin_stageA<<<ga, 128, 98304>>>(emb, chs[si], N);
    argmin_stageB<<<(N+255)/256, 256>>>(N, chs[si]);
    if (si < SN-1) upsample_kernel<<<NELEM/256, 256>>>(emb, pn);
    else           gather_kernel<<<NELEM/256, 256>>>(emb);
    conv_phi_kernel<<<dim3(8,32), 128>>>(f, pw + (size_t)kphi[si]*CC*CC*9, pb + kphi[si]*CC, si);
  }

  output_kernel<<<NELEM/256, 256>>>(f, out, out_size);
  loss_kernel<<<1, 32>>>(out, out_size);
}